// round 1
// baseline (speedup 1.0000x reference)
#include <cuda_runtime.h>
#include <cstdint>

#define NPROP 36864     // 64*64*9 proposals
#define NSORT 65536     // padded to pow2 for bitonic
#define NTOP  6000      // PRE_NMS_TOPN
#define NW    94        // ceil(6000/64) suppression words per row
#define NOUT  300       // POST_NMS_TOPN

// ---------------- scratch (device globals; no allocations allowed) ----------
__device__ float4             g_boxes[NPROP];
__device__ unsigned long long g_keys[NSORT];
__device__ float4             g_tbox[NTOP];
__device__ float              g_tarea[NTOP];
__device__ unsigned long long g_validbits[NW];
__device__ unsigned long long g_mask[(size_t)NTOP * NW];   // 4.5 MB

// Anchors for base_size=16, ratios (0.5,1,2) x scales (8,16,32), numpy-round
// (half-even) applied on host by hand. aw = x2-x1+1 = W, ah = H.
__constant__ float c_ax1[9] = {-84.f,-176.f,-360.f,-56.f,-120.f,-248.f,-36.f,-80.f,-168.f};
__constant__ float c_ay1[9] = {-40.f,-88.f,-184.f,-56.f,-120.f,-248.f,-80.f,-168.f,-344.f};
__constant__ float c_aw[9]  = {184.f,368.f,736.f,128.f,256.f,512.f,88.f,176.f,352.f};
__constant__ float c_ah[9]  = {96.f,192.f,384.f,128.f,256.f,512.f,176.f,352.f,704.f};

// ---------------- 1. decode proposals + build sort keys ---------------------
__global__ void prop_kernel(const float* __restrict__ scores,
                            const float* __restrict__ deltas) {
    int i = blockIdx.x * blockDim.x + threadIdx.x;
    if (i >= NSORT) return;
    if (i >= NPROP) { g_keys[i] = ~0ULL; return; }   // pad: sorts to the end

    int a   = i % 9;
    int pos = i / 9;                 // pos = h*64 + w
    int wx  = pos % 64;
    int hy  = pos / 64;
    float sx = (float)(wx * 16);
    float sy = (float)(hy * 16);

    const float* d = deltas + (size_t)pos * 36 + a * 4;
    float dx = d[0], dy = d[1], dw = d[2], dh = d[3];
    float score = scores[(size_t)pos * 18 + 9 + a];

    float aw = c_aw[a], ah = c_ah[a];
    // acx = (x1+shift) + 0.5*aw  (all exact integers/halves in fp32)
    float acx = __fadd_rn(__fadd_rn(c_ax1[a], sx), __fmul_rn(0.5f, aw));
    float acy = __fadd_rn(__fadd_rn(c_ay1[a], sy), __fmul_rn(0.5f, ah));

    float pcx = __fadd_rn(__fmul_rn(dx, aw), acx);
    float pcy = __fadd_rn(__fmul_rn(dy, ah), acy);
    float pw  = __fmul_rn(expf(dw), aw);
    float ph  = __fmul_rn(expf(dh), ah);

    float x1 = fminf(fmaxf(__fsub_rn(pcx, __fmul_rn(0.5f, pw)), 0.f), 1023.f);
    float y1 = fminf(fmaxf(__fsub_rn(pcy, __fmul_rn(0.5f, ph)), 0.f), 1023.f);
    float x2 = fminf(fmaxf(__fadd_rn(pcx, __fmul_rn(0.5f, pw)), 0.f), 1023.f);
    float y2 = fminf(fmaxf(__fadd_rn(pcy, __fmul_rn(0.5f, ph)), 0.f), 1023.f);

    float ws = __fadd_rn(__fsub_rn(x2, x1), 1.f);
    float hs = __fadd_rn(__fsub_rn(y2, y1), 1.f);
    bool valid = (ws >= 16.f) && (hs >= 16.f);

    g_boxes[i] = make_float4(x1, y1, x2, y2);

    // key: descending score, ties by ascending index (lax.top_k semantics).
    // scores are uniform[0,1) => nonneg => bits^0x80000000 is order-preserving.
    // invalid => -inf sentinel (0x007FFFFF == sortable(-inf)).
    unsigned fk = valid ? (__float_as_uint(score) ^ 0x80000000u) : 0x007FFFFFu;
    g_keys[i] = ((unsigned long long)(~fk) << 32) | (unsigned)i;
}

// ---------------- 2. bitonic sort of 65536 keys, ascending -------------------
__global__ void sort_local() {   // full bitonic up to k=2048 within a block
    __shared__ unsigned long long s[2048];
    int base = blockIdx.x * 2048;
    int t = threadIdx.x;
    s[t]        = g_keys[base + t];
    s[t + 1024] = g_keys[base + t + 1024];
    for (int k = 2; k <= 2048; k <<= 1) {
        for (int j = k >> 1; j > 0; j >>= 1) {
            __syncthreads();
            int p = ((t & ~(j - 1)) << 1) | (t & (j - 1));
            int q = p | j;
            bool asc = (((base + p) & k) == 0);
            unsigned long long a = s[p], b = s[q];
            if ((a > b) == asc) { s[p] = b; s[q] = a; }
        }
    }
    __syncthreads();
    g_keys[base + t]        = s[t];
    g_keys[base + t + 1024] = s[t + 1024];
}

__global__ void sort_global(int k, int j) {   // one global merge step
    int t = blockIdx.x * blockDim.x + threadIdx.x;   // 32768 threads
    int p = ((t & ~(j - 1)) << 1) | (t & (j - 1));
    int q = p | j;
    bool asc = ((p & k) == 0);
    unsigned long long a = g_keys[p], b = g_keys[q];
    if ((a > b) == asc) { g_keys[p] = b; g_keys[q] = a; }
}

__global__ void sort_tail(int k) {   // strides 1024..1 in shared memory
    __shared__ unsigned long long s[2048];
    int base = blockIdx.x * 2048;
    int t = threadIdx.x;
    s[t]        = g_keys[base + t];
    s[t + 1024] = g_keys[base + t + 1024];
    bool asc = ((base & k) == 0);   // uniform within a 2048 chunk (k >= 4096)
    for (int j = 1024; j > 0; j >>= 1) {
        __syncthreads();
        int p = ((t & ~(j - 1)) << 1) | (t & (j - 1));
        int q = p | j;
        unsigned long long a = s[p], b = s[q];
        if ((a > b) == asc) { s[p] = b; s[q] = a; }
    }
    __syncthreads();
    g_keys[base + t]        = s[t];
    g_keys[base + t + 1024] = s[t + 1024];
}

// ---------------- 3. gather top-6000 boxes / areas / validity ----------------
__global__ void gather_kernel() {
    int i = blockIdx.x * blockDim.x + threadIdx.x;
    if (i >= NTOP) return;
    unsigned long long key = g_keys[i];
    unsigned idx = (unsigned)key;
    float4 b = g_boxes[idx];
    g_tbox[i]  = b;
    g_tarea[i] = __fmul_rn(__fadd_rn(__fsub_rn(b.z, b.x), 1.f),
                           __fadd_rn(__fsub_rn(b.w, b.y), 1.f));
}

__global__ void validbits_kernel() {
    int w = blockIdx.x * blockDim.x + threadIdx.x;
    if (w >= NW) return;
    unsigned long long bits = 0;
    for (int b = 0; b < 64; b++) {
        int i = w * 64 + b;
        if (i < NTOP) {
            unsigned fk = ~(unsigned)(g_keys[i] >> 32);
            if (fk != 0x007FFFFFu) bits |= 1ULL << b;   // finite score
        }
    }
    g_validbits[w] = bits;
}

// ---------------- 4. NMS suppression matrix (upper triangle) -----------------
__global__ void mask_kernel() {
    int rb = blockIdx.x, cb = blockIdx.y;
    if (cb < rb) return;
    __shared__ float4 cbox[64];
    __shared__ float  carea[64];
    int t = threadIdx.x;
    int j0 = cb * 64;
    if (j0 + t < NTOP) { cbox[t] = g_tbox[j0 + t]; carea[t] = g_tarea[j0 + t]; }
    __syncthreads();
    int i = rb * 64 + t;
    if (i >= NTOP) return;
    float4 r = g_tbox[i];
    float  ra = g_tarea[i];
    int jmax = min(64, NTOP - j0);
    unsigned long long bits = 0;
    #pragma unroll 4
    for (int jj = 0; jj < jmax; jj++) {
        int j = j0 + jj;
        if (j <= i) continue;
        float4 c = cbox[jj];
        float xx1 = fmaxf(r.x, c.x);
        float yy1 = fmaxf(r.y, c.y);
        float xx2 = fminf(r.z, c.z);
        float yy2 = fminf(r.w, c.w);
        float iw = fmaxf(__fadd_rn(__fsub_rn(xx2, xx1), 1.f), 0.f);
        float ih = fmaxf(__fadd_rn(__fsub_rn(yy2, yy1), 1.f), 0.f);
        float inter = __fmul_rn(iw, ih);
        float denom = __fsub_rn(__fadd_rn(ra, carea[jj]), inter);
        float iou = __fdiv_rn(inter, denom);
        if (iou > 0.5f) bits |= 1ULL << jj;
    }
    g_mask[(size_t)i * NW + cb] = bits;
}

// ---------------- 5. sequential greedy scan + output -------------------------
__global__ void scan_kernel(float* __restrict__ out) {
    __shared__ unsigned long long remv[NW];
    __shared__ unsigned long long diag[64];    // mask[i][wb] for i in word wb
    __shared__ int kept[NOUT];
    __shared__ int cnt;
    __shared__ unsigned long long kwsh;
    int t = threadIdx.x;
    if (t < NW) remv[t] = 0ULL;
    if (t == 0) cnt = 0;
    if (t < 64) diag[t] = (t < NTOP) ? g_mask[(size_t)t * NW + 0] : 0ULL;
    __syncthreads();

    for (int wb = 0; wb < NW; wb++) {
        if (t == 0) {   // serial in-word pass, everything already in smem
            unsigned long long r  = remv[wb];
            unsigned long long vw = g_validbits[wb];
            unsigned long long kw = 0;
            int c  = cnt;
            int nb = min(64, NTOP - wb * 64);
            for (int b = 0; b < nb; b++) {
                if (((r >> b) & 1ULL) == 0 && ((vw >> b) & 1ULL)) {
                    kept[c++] = wb * 64 + b;
                    kw |= 1ULL << b;
                    r |= diag[b];               // suppress later j in this word
                    if (c == NOUT) break;       // later keeps can't matter
                }
            }
            cnt = c;
            kwsh = kw;
        }
        __syncthreads();
        if (cnt >= NOUT || wb == NW - 1) break;

        unsigned long long kw = kwsh;
        // parallel: OR kept rows into all future words; prefetch next diagonal
        for (int w = wb + 1 + t; w < NW; w += blockDim.x) {
            unsigned long long acc = remv[w];
            unsigned long long m = kw;
            while (m) {
                int b = __ffsll((long long)m) - 1;
                m &= m - 1;
                acc |= g_mask[(size_t)(wb * 64 + b) * NW + w];
            }
            remv[w] = acc;
        }
        if (t < 64) {
            int i = (wb + 1) * 64 + t;
            diag[t] = (i < NTOP) ? g_mask[(size_t)i * NW + (wb + 1)] : 0ULL;
        }
        __syncthreads();
    }
    __syncthreads();

    int c = cnt;
    const float inv = 0.0009765625f;   // 1/1024 (exact: matches /im_w)
    for (int o = t; o < NOUT; o += blockDim.x) {
        float4 b = make_float4(0.f, 0.f, 0.f, 0.f);
        if (o < c) {
            float4 bb = g_tbox[kept[o]];
            b.x = bb.x * inv; b.y = bb.y * inv; b.z = bb.z * inv; b.w = bb.w * inv;
        }
        out[o * 4 + 0] = b.x;
        out[o * 4 + 1] = b.y;
        out[o * 4 + 2] = b.z;
        out[o * 4 + 3] = b.w;
    }
}

// ---------------- launch ------------------------------------------------------
extern "C" void kernel_launch(void* const* d_in, const int* in_sizes, int n_in,
                              void* d_out, int out_size) {
    // scores: 1*64*64*18 = 73728 ; bbox_deltas: 1*64*64*36 = 147456
    const float* scores = (const float*)d_in[0];
    const float* deltas = (const float*)d_in[1];
    if (in_sizes[0] != 73728) {   // defensive: swap if metadata order differs
        scores = (const float*)d_in[1];
        deltas = (const float*)d_in[0];
    }
    float* out = (float*)d_out;

    prop_kernel<<<NSORT / 256, 256>>>(scores, deltas);

    sort_local<<<32, 1024>>>();
    for (int k = 4096; k <= NSORT; k <<= 1) {
        for (int j = k >> 1; j >= 2048; j >>= 1)
            sort_global<<<32768 / 256, 256>>>(k, j);
        sort_tail<<<32, 1024>>>(k);
    }

    gather_kernel<<<(NTOP + 255) / 256, 256>>>();
    validbits_kernel<<<2, 64>>>();

    dim3 mg(NW, NW);
    mask_kernel<<<mg, 64>>>();

    scan_kernel<<<1, 128>>>(out);
}